// round 4
// baseline (speedup 1.0000x reference)
#include <cuda_runtime.h>
#include <cstdint>

#define N 8192
#define D 64
#define E 262144

// Scratch (no allocations allowed — __device__ globals)
__device__ float g_sk[N * D];   // normalized state_K
__device__ float g_g[N];        // tanh(state_H)
__device__ float g_fk[N * D];   // f_K accumulator (pre-projection)
__device__ float g_zt[N];       // 0.5 * W_hop^T @ g accumulator

__device__ __forceinline__ void red_add_v4(float* p, float4 v) {
    asm volatile("red.global.add.v4.f32 [%0], {%1,%2,%3,%4};"
                 :: "l"(p), "f"(v.x), "f"(v.y), "f"(v.z), "f"(v.w)
                 : "memory");
}

// ---------------------------------------------------------------------------
// prep: sk = normalize(state_K rows), g = tanh(state_H), zero accumulators,
//       out_fH = -state_H.  grid 1024 x 256 : one warp per row of state_K.
// ---------------------------------------------------------------------------
__global__ void __launch_bounds__(256) prep_kernel(
    const float* __restrict__ stateH,
    const float* __restrict__ stateK,
    float* __restrict__ outH)
{
    int tid  = threadIdx.x;
    int gtid = blockIdx.x * 256 + tid;

    // zero f_K accumulator: 524288 floats = 262144 float2 = exactly grid size
    ((float2*)g_fk)[gtid] = make_float2(0.f, 0.f);

    int row  = gtid >> 5;           // 0..8191
    int lane = tid & 31;
    float2 v = ((const float2*)(stateK + (size_t)row * D))[lane];
    float ss = v.x * v.x + v.y * v.y;
    #pragma unroll
    for (int o = 16; o; o >>= 1) ss += __shfl_xor_sync(0xffffffffu, ss, o);
    float inv = rsqrtf(ss);
    ((float2*)(g_sk + (size_t)row * D))[lane] = make_float2(v.x * inv, v.y * inv);

    if (gtid < N) {
        float h = stateH[gtid];
        g_g[gtid]  = tanhf(h);
        g_zt[gtid] = 0.f;
        outH[gtid] = -h;
    }
}

// ---------------------------------------------------------------------------
// matvec: single pass over W_hop (256 MB) computing BOTH
//   y  = W_hop  @ g  (row dot products, block owns 16 full rows)
//   yT = W_hop^T @ g (column partials in registers, flushed via red.v4)
// f_H += 0.5*y (atomic per warp-partial), g_zt += 0.5*yT.
// grid 512 x 256, 16 rows/block, g cached in shared (32 KB).
// ---------------------------------------------------------------------------
__global__ void __launch_bounds__(256) matvec_kernel(
    const float* __restrict__ W,
    float* __restrict__ outH)
{
    __shared__ float4 gsh[N / 4];
    int tid = threadIdx.x;
    #pragma unroll
    for (int k = 0; k < 8; k++)
        gsh[tid + 256 * k] = ((const float4*)g_g)[tid + 256 * k];
    __syncthreads();
    const float* gs = (const float*)gsh;

    float4 va[8];
    #pragma unroll
    for (int k = 0; k < 8; k++) va[k] = make_float4(0.f, 0.f, 0.f, 0.f);

    int r0 = blockIdx.x * 16;
    for (int r = 0; r < 16; r++) {
        const float4* rowp = (const float4*)(W + (size_t)(r0 + r) * N);
        float gr = gs[r0 + r];
        float dp = 0.f;
        #pragma unroll
        for (int k = 0; k < 8; k++) {
            float4 w  = __ldcs(&rowp[tid + 256 * k]);   // streaming, evict-first
            float4 gv = gsh[tid + 256 * k];
            dp = fmaf(w.x, gv.x, dp); dp = fmaf(w.y, gv.y, dp);
            dp = fmaf(w.z, gv.z, dp); dp = fmaf(w.w, gv.w, dp);
            va[k].x = fmaf(w.x, gr, va[k].x);
            va[k].y = fmaf(w.y, gr, va[k].y);
            va[k].z = fmaf(w.z, gr, va[k].z);
            va[k].w = fmaf(w.w, gr, va[k].w);
        }
        #pragma unroll
        for (int o = 16; o; o >>= 1) dp += __shfl_xor_sync(0xffffffffu, dp, o);
        if ((tid & 31) == 0) atomicAdd(&outH[r0 + r], 0.5f * dp);
    }
    #pragma unroll
    for (int k = 0; k < 8; k++) {
        int i4 = tid + 256 * k;
        red_add_v4(g_zt + 4 * i4,
                   make_float4(0.5f * va[k].x, 0.5f * va[k].y,
                               0.5f * va[k].z, 0.5f * va[k].w));
    }
}

// ---------------------------------------------------------------------------
// edges: both lists fused. Half-warp (16 lanes, float4 each) per edge.
//   list K  (edge ids [0,E)):   s = <sk_a, sk_b>, coef = poly(s)
//   list HK (edge ids [E,2E)):  Gram = <sk_i, sk_j>, Wij = sym W,
//                               f_H atomic adds, coef = -g_i g_j Wij / kappa_K
// scatter: f_K[i] += coef*sk[j], f_K[j] += coef*sk[i]  via red.v4.
// grid 32768 x 256 (16 edges per block).
// ---------------------------------------------------------------------------
__global__ void __launch_bounds__(256) edge_kernel(
    const int* __restrict__ indK,
    const int* __restrict__ indHK,
    const float* __restrict__ W,
    const float* __restrict__ coeffs,
    const float* __restrict__ kKp,
    const float* __restrict__ kHp,
    float* __restrict__ outH)
{
    int gtid = blockIdx.x * 256 + threadIdx.x;
    int edge = gtid >> 4;               // half-warp id = edge id, [0, 2E)
    int l    = threadIdx.x & 15;

    bool isK = edge < E;
    int e2   = isK ? edge : edge - E;
    const int* ind = isK ? indK : indHK;
    int i = ind[2 * e2];
    int j = ind[2 * e2 + 1];

    float4 si = ((const float4*)(g_sk + (size_t)i * D))[l];
    float4 sj = ((const float4*)(g_sk + (size_t)j * D))[l];
    float dp = si.x * sj.x + si.y * sj.y + si.z * sj.z + si.w * sj.w;
    #pragma unroll
    for (int o = 8; o; o >>= 1) dp += __shfl_xor_sync(0xffffffffu, dp, o, 16);

    float coef;
    if (isK) {
        float c0 = coeffs[0], c1 = coeffs[1], c2 = coeffs[2], c3 = coeffs[3];
        coef = dp * (c0 + dp * (c1 + dp * (c2 + dp * c3)));
    } else {
        float wij = 0.5f * (W[(size_t)i * N + j] + W[(size_t)j * N + i]);
        float gi = g_g[i], gj = g_g[j];
        if (l == 0) {
            float ikH = 1.f / *kHp;
            atomicAdd(&outH[i], dp * wij * gj * ikH);
            atomicAdd(&outH[j], dp * wij * gi * ikH);
        }
        coef = -gi * gj * wij / *kKp;
    }

    red_add_v4(g_fk + (size_t)i * D + 4 * l,
               make_float4(coef * sj.x, coef * sj.y, coef * sj.z, coef * sj.w));
    red_add_v4(g_fk + (size_t)j * D + 4 * l,
               make_float4(coef * si.x, coef * si.y, coef * si.z, coef * si.w));
}

// ---------------------------------------------------------------------------
// final: f_H += zT;  f_K = -raw + sk * <sk, raw> + sk @ (omega - omega^T)/2.
// One warp per row. sk[r][d] comes from REGISTERS via shuffle (no broadcast
// LDS); Om loads explicitly batched 8-deep into registers (MLP=8). Dual
// accumulators break the FMA chain.  grid 1024 x 256 (8 rows per block).
// ---------------------------------------------------------------------------
__global__ void __launch_bounds__(256) final_kernel(
    const float* __restrict__ omega,
    float* __restrict__ out)
{
    __shared__ float Om[D * D];          // antisymmetrized, row-major Om[d][c]
    int tid = threadIdx.x;
    #pragma unroll
    for (int t = tid; t < D * D; t += 256) {
        int d = t >> 6, c = t & 63;
        Om[t] = 0.5f * (omega[t] - omega[c * D + d]);
    }
    __syncthreads();

    int w    = tid >> 5;
    int lane = tid & 31;
    int r    = blockIdx.x * 8 + w;

    float2 raw = ((const float2*)(g_fk + (size_t)r * D))[lane];
    float2 skr = ((const float2*)(g_sk + (size_t)r * D))[lane];

    int gtid = blockIdx.x * 256 + tid;
    if (gtid < N) out[gtid] += g_zt[gtid];   // finish f_H

    float dp = skr.x * raw.x + skr.y * raw.y;
    #pragma unroll
    for (int o = 16; o; o >>= 1) dp += __shfl_xor_sync(0xffffffffu, dp, o);

    // acc[c] = sum_d sk[r][d] * Om[d][c]; lane owns cols {2*lane, 2*lane+1}.
    // sk[r][d] lives in lane (d>>1)'s skr.{x|y} -> shuffle broadcast.
    const float2* Om2 = (const float2*)Om;
    float ax0 = 0.f, ay0 = 0.f, ax1 = 0.f, ay1 = 0.f;
    #pragma unroll
    for (int dd = 0; dd < D; dd += 8) {
        float2 om[8];
        #pragma unroll
        for (int q = 0; q < 8; q++)
            om[q] = Om2[(dd + q) * 32 + lane];     // 8 independent LDS.64
        #pragma unroll
        for (int q = 0; q < 8; q++) {
            int d = dd + q;                         // compile-time constant
            float s = __shfl_sync(0xffffffffu, (d & 1) ? skr.y : skr.x, d >> 1);
            if (q & 1) { ax1 = fmaf(s, om[q].x, ax1); ay1 = fmaf(s, om[q].y, ay1); }
            else       { ax0 = fmaf(s, om[q].x, ax0); ay0 = fmaf(s, om[q].y, ay0); }
        }
    }
    float accx = ax0 + ax1;
    float accy = ay0 + ay1;

    float2 o2;
    o2.x = -raw.x + skr.x * dp + accx;
    o2.y = -raw.y + skr.y * dp + accy;
    ((float2*)(out + N))[r * 32 + lane] = o2;
}

// ---------------------------------------------------------------------------
extern "C" void kernel_launch(void* const* d_in, const int* in_sizes, int n_in,
                              void* d_out, int out_size)
{
    const float* stateH = (const float*)d_in[0];
    const float* stateK = (const float*)d_in[1];
    const float* W      = (const float*)d_in[2];
    const float* coeffs = (const float*)d_in[3];
    const float* omega  = (const float*)d_in[4];
    const int*   indK   = (const int*)  d_in[5];
    const int*   indHK  = (const int*)  d_in[6];
    const float* kK     = (const float*)d_in[7];
    const float* kH     = (const float*)d_in[8];
    float* out = (float*)d_out;

    prep_kernel  <<<1024, 256>>>(stateH, stateK, out);
    matvec_kernel<<<512,  256>>>(W, out);
    edge_kernel  <<<32768, 256>>>(indK, indHK, W, coeffs, kK, kH, out);
    final_kernel <<<1024, 256>>>(omega, out);
}

// round 5
// speedup vs baseline: 1.0795x; 1.0795x over previous
#include <cuda_runtime.h>
#include <cstdint>

#define N 8192
#define D 64
#define E 262144

// Scratch (no allocations allowed — __device__ globals)
__device__ float g_sk[N * D];   // normalized state_K
__device__ float g_g[N];        // tanh(state_H)
__device__ float g_fk[N * D];   // f_K accumulator (pre-projection)
__device__ float g_zt[N];       // 0.5 * W_hop^T @ g accumulator

__device__ __forceinline__ void red_add_v4(float* p, float4 v) {
    asm volatile("red.global.add.v4.f32 [%0], {%1,%2,%3,%4};"
                 :: "l"(p), "f"(v.x), "f"(v.y), "f"(v.z), "f"(v.w)
                 : "memory");
}

// ---------------------------------------------------------------------------
// prep: sk = normalize(state_K rows), g = tanh(state_H), zero accumulators,
//       out_fH = -state_H.  grid 1024 x 256 : one warp per row of state_K.
// ---------------------------------------------------------------------------
__global__ void __launch_bounds__(256) prep_kernel(
    const float* __restrict__ stateH,
    const float* __restrict__ stateK,
    float* __restrict__ outH)
{
    int tid  = threadIdx.x;
    int gtid = blockIdx.x * 256 + tid;

    // zero f_K accumulator: 524288 floats = 262144 float2 = exactly grid size
    ((float2*)g_fk)[gtid] = make_float2(0.f, 0.f);

    int row  = gtid >> 5;           // 0..8191
    int lane = tid & 31;
    float2 v = ((const float2*)(stateK + (size_t)row * D))[lane];
    float ss = v.x * v.x + v.y * v.y;
    #pragma unroll
    for (int o = 16; o; o >>= 1) ss += __shfl_xor_sync(0xffffffffu, ss, o);
    float inv = rsqrtf(ss);
    ((float2*)(g_sk + (size_t)row * D))[lane] = make_float2(v.x * inv, v.y * inv);

    if (gtid < N) {
        float h = stateH[gtid];
        g_g[gtid]  = tanhf(h);
        g_zt[gtid] = 0.f;
        outH[gtid] = -h;
    }
}

// ---------------------------------------------------------------------------
// matvec: single pass over W_hop (256 MB) computing BOTH
//   y  = W_hop  @ g  (row dot products, block owns 16 full rows)
//   yT = W_hop^T @ g (column partials in registers, flushed via red.v4)
// f_H += 0.5*y (atomic per warp-partial), g_zt += 0.5*yT.
// grid 512 x 256, 16 rows/block, g cached in shared (32 KB).
// ---------------------------------------------------------------------------
__global__ void __launch_bounds__(256) matvec_kernel(
    const float* __restrict__ W,
    float* __restrict__ outH)
{
    __shared__ float4 gsh[N / 4];
    int tid = threadIdx.x;
    #pragma unroll
    for (int k = 0; k < 8; k++)
        gsh[tid + 256 * k] = ((const float4*)g_g)[tid + 256 * k];
    __syncthreads();
    const float* gs = (const float*)gsh;

    float4 va[8];
    #pragma unroll
    for (int k = 0; k < 8; k++) va[k] = make_float4(0.f, 0.f, 0.f, 0.f);

    int r0 = blockIdx.x * 16;
    for (int r = 0; r < 16; r++) {
        const float4* rowp = (const float4*)(W + (size_t)(r0 + r) * N);
        float gr = gs[r0 + r];
        float dp = 0.f;
        #pragma unroll
        for (int k = 0; k < 8; k++) {
            float4 w  = __ldcs(&rowp[tid + 256 * k]);   // streaming, evict-first
            float4 gv = gsh[tid + 256 * k];
            dp = fmaf(w.x, gv.x, dp); dp = fmaf(w.y, gv.y, dp);
            dp = fmaf(w.z, gv.z, dp); dp = fmaf(w.w, gv.w, dp);
            va[k].x = fmaf(w.x, gr, va[k].x);
            va[k].y = fmaf(w.y, gr, va[k].y);
            va[k].z = fmaf(w.z, gr, va[k].z);
            va[k].w = fmaf(w.w, gr, va[k].w);
        }
        #pragma unroll
        for (int o = 16; o; o >>= 1) dp += __shfl_xor_sync(0xffffffffu, dp, o);
        if ((tid & 31) == 0) atomicAdd(&outH[r0 + r], 0.5f * dp);
    }
    #pragma unroll
    for (int k = 0; k < 8; k++) {
        int i4 = tid + 256 * k;
        red_add_v4(g_zt + 4 * i4,
                   make_float4(0.5f * va[k].x, 0.5f * va[k].y,
                               0.5f * va[k].z, 0.5f * va[k].w));
    }
}

// ---------------------------------------------------------------------------
// edges: both lists fused. Half-warp (16 lanes, float4 each) per edge.
//   list K  (edge ids [0,E)):   s = <sk_a, sk_b>, coef = poly(s)
//   list HK (edge ids [E,2E)):  Gram = <sk_i, sk_j>, Wij = sym W,
//                               f_H atomic adds, coef = -g_i g_j Wij / kappa_K
// scatter: f_K[i] += coef*sk[j], f_K[j] += coef*sk[i]  via red.v4.
// grid 32768 x 256 (16 edges per block).
// ---------------------------------------------------------------------------
__global__ void __launch_bounds__(256) edge_kernel(
    const int* __restrict__ indK,
    const int* __restrict__ indHK,
    const float* __restrict__ W,
    const float* __restrict__ coeffs,
    const float* __restrict__ kKp,
    const float* __restrict__ kHp,
    float* __restrict__ outH)
{
    int gtid = blockIdx.x * 256 + threadIdx.x;
    int edge = gtid >> 4;               // half-warp id = edge id, [0, 2E)
    int l    = threadIdx.x & 15;

    bool isK = edge < E;
    int e2   = isK ? edge : edge - E;
    const int* ind = isK ? indK : indHK;
    int i = ind[2 * e2];
    int j = ind[2 * e2 + 1];

    float4 si = ((const float4*)(g_sk + (size_t)i * D))[l];
    float4 sj = ((const float4*)(g_sk + (size_t)j * D))[l];
    float dp = si.x * sj.x + si.y * sj.y + si.z * sj.z + si.w * sj.w;
    #pragma unroll
    for (int o = 8; o; o >>= 1) dp += __shfl_xor_sync(0xffffffffu, dp, o, 16);

    float coef;
    if (isK) {
        float c0 = coeffs[0], c1 = coeffs[1], c2 = coeffs[2], c3 = coeffs[3];
        coef = dp * (c0 + dp * (c1 + dp * (c2 + dp * c3)));
    } else {
        float wij = 0.5f * (W[(size_t)i * N + j] + W[(size_t)j * N + i]);
        float gi = g_g[i], gj = g_g[j];
        if (l == 0) {
            float ikH = 1.f / *kHp;
            atomicAdd(&outH[i], dp * wij * gj * ikH);
            atomicAdd(&outH[j], dp * wij * gi * ikH);
        }
        coef = -gi * gj * wij / *kKp;
    }

    red_add_v4(g_fk + (size_t)i * D + 4 * l,
               make_float4(coef * sj.x, coef * sj.y, coef * sj.z, coef * sj.w));
    red_add_v4(g_fk + (size_t)j * D + 4 * l,
               make_float4(coef * si.x, coef * si.y, coef * si.z, coef * si.w));
}

// ---------------------------------------------------------------------------
// final: f_H += zT;  f_K = -raw + sk * <sk, raw> + sk @ (omega - omega^T)/2.
// grid 512 x 256; each warp handles 2 rows (block = 16 rows).
//  * global row loads issued FIRST (DRAM latency overlaps Om staging + sync)
//  * Om staged once per block, one LDS.64 feeds both rows (2x FMA per LDS)
//  * __launch_bounds__(256,1): no register cap, no spill of the row regs
// ---------------------------------------------------------------------------
#define FB 512                      // final grid
#define RPW 2                       // rows per warp

__global__ void __launch_bounds__(256, 1) final_kernel(
    const float* __restrict__ omega,
    float* __restrict__ out)
{
    __shared__ float Om[D * D];          // antisymmetrized, row-major Om[d][c]
    int tid  = threadIdx.x;
    int w    = tid >> 5;
    int lane = tid & 31;
    int rbase = blockIdx.x * (8 * RPW) + w * RPW;

    // ---- prefetch the per-row global data before touching shared ----
    float2 raw[RPW], skr[RPW];
    #pragma unroll
    for (int rr = 0; rr < RPW; rr++) {
        raw[rr] = ((const float2*)(g_fk + (size_t)(rbase + rr) * D))[lane];
        skr[rr] = ((const float2*)(g_sk + (size_t)(rbase + rr) * D))[lane];
    }
    // f_H += zT : 8192 / 512 blocks = 16 elems per block
    if (tid < N / FB) {
        int hidx = blockIdx.x * (N / FB) + tid;
        out[hidx] += g_zt[hidx];
    }

    // ---- stage antisymmetrized Omega (runs while prefetches are in flight) --
    #pragma unroll
    for (int t = tid; t < D * D; t += 256) {
        int d = t >> 6, c = t & 63;
        Om[t] = 0.5f * (omega[t] - omega[c * D + d]);
    }
    __syncthreads();

    // ---- dp[rr] = <sk_r, raw_r> (independent shfl trees, interleaved) ----
    float dp[RPW];
    #pragma unroll
    for (int rr = 0; rr < RPW; rr++)
        dp[rr] = skr[rr].x * raw[rr].x + skr[rr].y * raw[rr].y;
    #pragma unroll
    for (int o = 16; o; o >>= 1) {
        #pragma unroll
        for (int rr = 0; rr < RPW; rr++)
            dp[rr] += __shfl_xor_sync(0xffffffffu, dp[rr], o);
    }

    // ---- acc[rr][c] = sum_d sk[r][d] * Om[d][c]; lane owns cols {2l,2l+1}.
    // One Om LDS.64 per d feeds RPW rows; sk[r][d] via register shuffle. ----
    const float2* Om2 = (const float2*)Om;
    float ax[RPW], ay[RPW];
    #pragma unroll
    for (int rr = 0; rr < RPW; rr++) { ax[rr] = 0.f; ay[rr] = 0.f; }
    #pragma unroll
    for (int d = 0; d < D; d++) {
        float2 o = Om2[d * 32 + lane];          // contiguous, conflict-free
        #pragma unroll
        for (int rr = 0; rr < RPW; rr++) {
            float s = __shfl_sync(0xffffffffu,
                                  (d & 1) ? skr[rr].y : skr[rr].x, d >> 1);
            ax[rr] = fmaf(s, o.x, ax[rr]);
            ay[rr] = fmaf(s, o.y, ay[rr]);
        }
    }

    #pragma unroll
    for (int rr = 0; rr < RPW; rr++) {
        float2 o2;
        o2.x = -raw[rr].x + skr[rr].x * dp[rr] + ax[rr];
        o2.y = -raw[rr].y + skr[rr].y * dp[rr] + ay[rr];
        ((float2*)(out + N))[(rbase + rr) * 32 + lane] = o2;
    }
}

// ---------------------------------------------------------------------------
extern "C" void kernel_launch(void* const* d_in, const int* in_sizes, int n_in,
                              void* d_out, int out_size)
{
    const float* stateH = (const float*)d_in[0];
    const float* stateK = (const float*)d_in[1];
    const float* W      = (const float*)d_in[2];
    const float* coeffs = (const float*)d_in[3];
    const float* omega  = (const float*)d_in[4];
    const int*   indK   = (const int*)  d_in[5];
    const int*   indHK  = (const int*)  d_in[6];
    const float* kK     = (const float*)d_in[7];
    const float* kH     = (const float*)d_in[8];
    float* out = (float*)d_out;

    prep_kernel  <<<1024, 256>>>(stateH, stateK, out);
    matvec_kernel<<<512,  256>>>(W, out);
    edge_kernel  <<<32768, 256>>>(indK, indHK, W, coeffs, kK, kH, out);
    final_kernel <<<FB, 256>>>(omega, out);
}